// round 2
// baseline (speedup 1.0000x reference)
#include <cuda_runtime.h>
#include <math.h>

// Problem constants (fixed shapes)
#define NPIX 65536              // 256*256
#define TWO_PI 6.283185307179586f

// ---------------- scratch (device globals: allocation-free rule) -------------
__device__ float2 g_fA[9 * NPIX];     // filters spatial -> hat (ping)
__device__ float2 g_fB[9 * NPIX];     // filters (pong)
__device__ float2 g_xT[8 * NPIX];     // x row-FFT tmp
__device__ float2 g_Xh[8 * NPIX];     // fft2(x)
__device__ float  g_U1[64 * NPIX];    // |ifft2(Xh*psi)| real
__device__ float2 g_U1h[64 * NPIX];   // fft2(U1)
__device__ float2 g_S[512 * NPIX];    // big reusable complex scratch (256MB)
__device__ float  g_gs[8];
__device__ float2 g_ws[8];

// ---------------- small helpers ----------------------------------------------
__device__ __forceinline__ int sw(int q) { return q + (q >> 3); }  // smem pad
#define LINE_PAD 288

__device__ __forceinline__ float2 cmulf(float2 a, float2 b) {
  return make_float2(a.x * b.x - a.y * b.y, a.x * b.y + a.y * b.x);
}

// 256-pt Stockham radix-4 FFT on one smem line; 64 threads (lane=0..63).
// sgn = -1 forward, +1 inverse (unscaled). Result ends in A, in natural order.
// Block-wide __syncthreads inside — all threads of the block must call this.
__device__ __forceinline__ void fft256_line(float2* A, float2* B, int lane, float sgn) {
  float2* a = A;
  float2* b = B;
  int L = 1;
#pragma unroll
  for (int st = 0; st < 4; ++st) {
    float2 v0 = a[sw(lane)];
    float2 v1 = a[sw(lane + 64)];
    float2 v2 = a[sw(lane + 128)];
    float2 v3 = a[sw(lane + 192)];
    int j = lane & (L - 1);
    int kk = lane >> (2 * st);
    if (st) {
      float ang = sgn * TWO_PI * (float)j / (float)(4 * L);
      float sn, cs;
      __sincosf(ang, &sn, &cs);
      float2 w1 = make_float2(cs, sn);
      float2 w2 = cmulf(w1, w1);
      float2 w3 = cmulf(w2, w1);
      v1 = cmulf(v1, w1);
      v2 = cmulf(v2, w2);
      v3 = cmulf(v3, w3);
    }
    float2 t0 = make_float2(v0.x + v2.x, v0.y + v2.y);
    float2 t1 = make_float2(v0.x - v2.x, v0.y - v2.y);
    float2 t2 = make_float2(v1.x + v3.x, v1.y + v3.y);
    float2 t3 = make_float2(v1.x - v3.x, v1.y - v3.y);
    float2 wt = make_float2(-sgn * t3.y, sgn * t3.x);  // (sgn*i)*t3
    int base = (kk << (2 * st + 2)) + j;
    b[sw(base)]         = make_float2(t0.x + t2.x, t0.y + t2.y);
    b[sw(base + L)]     = make_float2(t1.x + wt.x, t1.y + wt.y);
    b[sw(base + 2 * L)] = make_float2(t0.x - t2.x, t0.y - t2.y);
    b[sw(base + 3 * L)] = make_float2(t1.x - wt.x, t1.y - wt.y);
    __syncthreads();
    float2* t = a; a = b; b = t;
    L <<= 2;
  }
}

// ---------------- filter construction -----------------------------------------
__global__ void k_filter_sums(const float* theta, const float* xis,
                              const float* sigmas, const float* slants) {
  int f = blockIdx.x;
  float th = theta[f], xi = xis[f], sg = sigmas[f], sl = slants[f];
  float c = cosf(th), s = sinf(th);
  float a0 = sl / sg, a1 = 1.f / sg;
  float gsum = 0.f, wr = 0.f, wi = 0.f;
  for (int p = threadIdx.x; p < NPIX; p += 256) {
    float gm = (float)((p >> 8) - 128);
    float gn = (float)((p & 255) - 128);
    float u = c * gm + s * gn;
    float v = -s * gm + c * gn;
    float g = expf(-0.5f * (a0 * a0 * u * u + a1 * a1 * v * v));
    float sn, cn;
    sincosf(xi * u, &sn, &cn);
    gsum += g;
    wr += cn * g;
    wi += sn * g;
  }
  __shared__ float r0[256], r1[256], r2[256];
  int tid = threadIdx.x;
  r0[tid] = gsum; r1[tid] = wr; r2[tid] = wi;
  __syncthreads();
  for (int s2 = 128; s2 > 0; s2 >>= 1) {
    if (tid < s2) { r0[tid] += r0[tid + s2]; r1[tid] += r1[tid + s2]; r2[tid] += r2[tid + s2]; }
    __syncthreads();
  }
  if (tid == 0) { g_gs[f] = r0[0]; g_ws[f] = make_float2(r1[0], r2[0]); }
}

// Writes spatial filters with ifftshift baked into the index -> g_fA
// f in [0,8): Morlet psi; f == 8: low-pass phi (gabor, sigma=3.2).
__global__ void k_filter_build(const float* theta, const float* xis,
                               const float* sigmas, const float* slants) {
  int gid = blockIdx.x * 256 + threadIdx.x;  // 0 .. 9*NPIX-1
  int f = gid >> 16;
  int p = gid & 65535;
  int i = p >> 8, jd = p & 255;
  float gm = (i < 128) ? (float)i : (float)(i - 256);
  float gn = (jd < 128) ? (float)jd : (float)(jd - 256);
  float2 val;
  if (f < 8) {
    float th = theta[f], xi = xis[f], sg = sigmas[f], sl = slants[f];
    float c = cosf(th), s = sinf(th);
    float u = c * gm + s * gn;
    float v = -s * gm + c * gn;
    float a0 = sl / sg, a1 = 1.f / sg;
    float g = expf(-0.5f * (a0 * a0 * u * u + a1 * a1 * v * v));
    float sn, cn;
    sincosf(xi * u, &sn, &cn);
    float Kr = g_ws[f].x / g_gs[f];
    float Ki = g_ws[f].y / g_gs[f];
    float invn = sl / (TWO_PI * sg * sg);  // 1/norm
    val = make_float2((cn - Kr) * g * invn, (sn - Ki) * g * invn);
  } else {
    const float sp = 3.2f;  // 0.8 * 2^J
    float g = expf(-0.5f * (gm * gm + gn * gn) / (sp * sp));
    val = make_float2(g / (TWO_PI * sp * sp), 0.f);
  }
  g_fA[gid] = val;
}

// ---------------- FFT passes ---------------------------------------------------
// Forward row pass (contiguous axis). 4 rows/block, 256 threads.
template <bool REAL_IN>
__global__ void k_fft_rows_f(const void* in_, float2* out) {
  __shared__ float2 SA[4][LINE_PAD], SB[4][LINE_PAD];
  int sub = threadIdx.x >> 6, lane = threadIdx.x & 63;
  size_t row = (size_t)blockIdx.x * 4 + sub;
  size_t base = row << 8;
  if (REAL_IN) {
    const float* in = (const float*)in_;
#pragma unroll
    for (int r = 0; r < 4; ++r)
      SA[sub][sw(lane + 64 * r)] = make_float2(in[base + lane + 64 * r], 0.f);
  } else {
    const float2* in = (const float2*)in_;
#pragma unroll
    for (int r = 0; r < 4; ++r)
      SA[sub][sw(lane + 64 * r)] = in[base + lane + 64 * r];
  }
  fft256_line(SA[sub], SB[sub], lane, -1.f);
#pragma unroll
  for (int r = 0; r < 4; ++r)
    out[base + lane + 64 * r] = SA[sub][sw(lane + 64 * r)];
}

// Forward column pass (stride-256 axis). 4 cols/block; 64 blocks per image.
__global__ void k_fft_cols_f(const float2* in, float2* out) {
  __shared__ float2 SA[4][LINE_PAD], SB[4][LINE_PAD];
  int line = threadIdx.x & 3, lane = threadIdx.x >> 2;
  int img = blockIdx.x >> 6;
  int col = ((blockIdx.x & 63) << 2) + line;
  size_t base = ((size_t)img << 16) + col;
#pragma unroll
  for (int r = 0; r < 4; ++r)
    SA[line][sw(lane + 64 * r)] = in[base + ((size_t)(lane + 64 * r) << 8)];
  fft256_line(SA[line], SB[line], lane, -1.f);
#pragma unroll
  for (int r = 0; r < 4; ++r)
    out[base + ((size_t)(lane + 64 * r) << 8)] = SA[line][sw(lane + 64 * r)];
}

// Inverse column pass fused with pointwise filter multiply (+ 1/65536 scale).
// Output image o reads input image (o >> LOGNF) and filter (o & (2^LOGNF-1)).
template <int LOGNF>
__global__ void k_icolmul(const float2* in, const float2* filt, float2* out, float scale) {
  __shared__ float2 SA[4][LINE_PAD], SB[4][LINE_PAD];
  int line = threadIdx.x & 3, lane = threadIdx.x >> 2;
  int o = blockIdx.x >> 6;
  int col = ((blockIdx.x & 63) << 2) + line;
  const float2* src = in + ((size_t)(o >> LOGNF) << 16);
  const float2* ff = filt + ((size_t)(o & ((1 << LOGNF) - 1)) << 16);
#pragma unroll
  for (int r = 0; r < 4; ++r) {
    size_t a = col + ((size_t)(lane + 64 * r) << 8);
    float2 v = cmulf(src[a], ff[a]);
    SA[line][sw(lane + 64 * r)] = make_float2(v.x * scale, v.y * scale);
  }
  fft256_line(SA[line], SB[line], lane, 1.f);
  size_t obase = ((size_t)o << 16) + col;
#pragma unroll
  for (int r = 0; r < 4; ++r)
    out[obase + ((size_t)(lane + 64 * r) << 8)] = SA[line][sw(lane + 64 * r)];
}

// Inverse row pass fused with abs/real extraction and scatter into the output
// channel layout out[b, c*73 + ch, m, n].  STAGE: 0=S0(real), 1=U1(abs,+u1buf), 2=U2(abs)
template <int STAGE>
__global__ void k_irows_out(const float2* in, float* out, float* u1) {
  __shared__ float2 SA[4][LINE_PAD], SB[4][LINE_PAD];
  int sub = threadIdx.x >> 6, lane = threadIdx.x & 63;
  size_t gl = (size_t)blockIdx.x * 4 + sub;
  int o = (int)(gl >> 8);
  int row = (int)(gl & 255);
  size_t base = gl << 8;
#pragma unroll
  for (int r = 0; r < 4; ++r)
    SA[sub][sw(lane + 64 * r)] = in[base + lane + 64 * r];
  fft256_line(SA[sub], SB[sub], lane, 1.f);

  int b, ch;
  if (STAGE == 0) {
    b = o >> 1; ch = (o & 1) * 73;
  } else if (STAGE == 1) {
    int f = o & 7, bc = o >> 3;
    b = bc >> 1; ch = (bc & 1) * 73 + 1 + f;
  } else {
    int f2 = o & 7, t = o >> 3;
    int f1 = t & 7, bc = t >> 3;
    b = bc >> 1; ch = (bc & 1) * 73 + 9 + f1 * 8 + f2;
  }
  size_t obase = (((size_t)(b * 146 + ch)) << 16) + ((size_t)row << 8);
#pragma unroll
  for (int r = 0; r < 4; ++r) {
    float2 v = SA[sub][sw(lane + 64 * r)];
    float val = (STAGE == 0) ? v.x : sqrtf(v.x * v.x + v.y * v.y);
    out[obase + lane + 64 * r] = val;
    if (STAGE == 1) u1[base + lane + 64 * r] = val;
  }
}

// ---------------- launch -------------------------------------------------------
extern "C" void kernel_launch(void* const* d_in, const int* in_sizes, int n_in,
                              void* d_out, int out_size) {
  (void)in_sizes; (void)n_in; (void)out_size;
  const float* x = (const float*)d_in[0];
  const float* theta = (const float*)d_in[1];
  const float* xis = (const float*)d_in[2];
  const float* sigmas = (const float*)d_in[3];
  const float* slants = (const float*)d_in[4];
  float* out = (float*)d_out;

  void* p;
  cudaGetSymbolAddress(&p, g_fA);  float2* fA = (float2*)p;
  cudaGetSymbolAddress(&p, g_fB);  float2* fB = (float2*)p;
  cudaGetSymbolAddress(&p, g_xT);  float2* xT = (float2*)p;
  cudaGetSymbolAddress(&p, g_Xh);  float2* Xh = (float2*)p;
  cudaGetSymbolAddress(&p, g_U1);  float* U1 = (float*)p;
  cudaGetSymbolAddress(&p, g_U1h); float2* U1h = (float2*)p;
  cudaGetSymbolAddress(&p, g_S);   float2* S = (float2*)p;

  const float inv = 1.f / 65536.f;

  // Filters: spatial build (+ifftshift) then forward FFT. psi_hat = fA[0..8), phi_hat = fA[8]
  k_filter_sums<<<8, 256>>>(theta, xis, sigmas, slants);
  k_filter_build<<<(9 * NPIX) / 256, 256>>>(theta, xis, sigmas, slants);
  k_fft_rows_f<false><<<9 * 64, 256>>>(fA, fB);
  k_fft_cols_f<<<9 * 64, 256>>>(fB, fA);

  // Xh = fft2(x)  (8 real images)
  k_fft_rows_f<true><<<8 * 64, 256>>>(x, xT);
  k_fft_cols_f<<<8 * 64, 256>>>(xT, Xh);

  // S0 = ifft2(Xh * phi).real
  k_icolmul<0><<<8 * 64, 256>>>(Xh, fA + 8 * NPIX, S, inv);
  k_irows_out<0><<<8 * 64, 256>>>(S, out, nullptr);

  // U1 = |ifft2(Xh x psi)|  (64 images) -> out channels + U1 buffer
  k_icolmul<3><<<64 * 64, 256>>>(Xh, fA, S, inv);
  k_irows_out<1><<<64 * 64, 256>>>(S, out, U1);

  // U1h = fft2(U1)
  k_fft_rows_f<true><<<64 * 64, 256>>>(U1, S);
  k_fft_cols_f<<<64 * 64, 256>>>(S, U1h);

  // U2 = |ifft2(U1h x psi)|  (512 images) -> out channels
  k_icolmul<3><<<512 * 64, 256>>>(U1h, fA, S, inv);
  k_irows_out<2><<<512 * 64, 256>>>(S, out, nullptr);
}

// round 3
// speedup vs baseline: 2.2430x; 2.2430x over previous
#include <cuda_runtime.h>
#include <math.h>

#define NPIX 65536
#define TWO_PI 6.283185307179586f
#define LSTRIDE 273   // per-line smem stride (float2), 273 mod 16 = 1 -> conflict-free across lines

// ---------------- scratch (device globals: allocation-free rule) -------------
__device__ float2 g_fA[9 * NPIX];
__device__ float2 g_fB[9 * NPIX];
__device__ float2 g_xT[8 * NPIX];
__device__ float2 g_Xh[8 * NPIX];
__device__ float  g_U1[64 * NPIX];
__device__ float2 g_U1h[64 * NPIX];
__device__ float2 g_S[512 * NPIX];
__device__ float  g_gs[8];
__device__ float2 g_ws[8];

__device__ __forceinline__ float2 cmulf(float2 a, float2 b) {
  return make_float2(a.x * b.x - a.y * b.y, a.x * b.y + a.y * b.x);
}
__device__ __forceinline__ float2 cadd(float2 a, float2 b){ return make_float2(a.x+b.x, a.y+b.y); }
__device__ __forceinline__ float2 csub(float2 a, float2 b){ return make_float2(a.x-b.x, a.y-b.y); }

template<int SGN>
__device__ __forceinline__ void dft4(float2& x0, float2& x1, float2& x2, float2& x3){
  float2 t0 = cadd(x0,x2), t1 = csub(x0,x2);
  float2 t2 = cadd(x1,x3), t3 = csub(x1,x3);
  float2 it3 = make_float2(-(float)SGN * t3.y, (float)SGN * t3.x);  // SGN*i*t3
  x0 = cadd(t0,t2);
  x1 = cadd(t1,it3);
  x2 = csub(t0,t2);
  x3 = csub(t1,it3);
}

// 16-pt DFT fully in registers. Input v[n] natural order.
// Output: y[k0 + 4*k1] lands in v[4*k0 + k1]  (use PERM to read linearly).
#define PERM(k) ((((k)&3)<<2)|((k)>>2))
template<int SGN>
__device__ __forceinline__ void fft16(float2 v[16]){
  const float C[10] = {1.f, 0.9238795325f, 0.7071067812f, 0.3826834324f, 0.f,
                       -0.3826834324f, -0.7071067812f, -0.9238795325f, -1.f, -0.9238795325f};
  const float S[10] = {0.f, 0.3826834324f, 0.7071067812f, 0.9238795325f, 1.f,
                       0.9238795325f, 0.7071067812f, 0.3826834324f, 0.f, -0.3826834324f};
#pragma unroll
  for (int n0 = 0; n0 < 4; ++n0)
    dft4<SGN>(v[n0], v[4+n0], v[8+n0], v[12+n0]);   // A[n0][k0] -> v[n0+4*k0]
#pragma unroll
  for (int n0 = 1; n0 < 4; ++n0)
#pragma unroll
    for (int k0 = 1; k0 < 4; ++k0) {
      int m = n0 * k0;
      float2 w = make_float2(C[m], (float)SGN * S[m]);
      v[n0 + 4*k0] = cmulf(v[n0 + 4*k0], w);
    }
#pragma unroll
  for (int k0 = 0; k0 < 4; ++k0)
    dft4<SGN>(v[4*k0+0], v[4*k0+1], v[4*k0+2], v[4*k0+3]); // y[k0+4k1] -> v[4k0+k1]
}

// 256-pt FFT: fft16 + twiddle + one smem transpose + fft16.
// t in [0,16): thread's index within the line. sm: this line's 273-float2 buffer.
// On exit: X[t + 16*k2] is in v[PERM(k2)].
template<int SGN, bool BSYNC>
__device__ __forceinline__ void fft256_reg(float2 v[16], float2* sm, int t){
  fft16<SGN>(v);
  float ang = (float)SGN * TWO_PI * (float)t * (1.f / 256.f);
  float sn, cs; __sincosf(ang, &sn, &cs);
  float2 w = make_float2(cs, sn);
  float2 tw = make_float2(1.f, 0.f);
#pragma unroll
  for (int k1 = 0; k1 < 16; ++k1) {
    sm[k1 * 17 + t] = cmulf(v[PERM(k1)], tw);
    tw = cmulf(tw, w);
  }
  if (BSYNC) __syncthreads(); else __syncwarp();
#pragma unroll
  for (int n2 = 0; n2 < 16; ++n2) v[n2] = sm[t * 17 + n2];
  fft16<SGN>(v);
}

// ---------------- filter construction -----------------------------------------
__global__ void k_filter_sums(const float* theta, const float* xis,
                              const float* sigmas, const float* slants) {
  int f = blockIdx.x;
  float th = theta[f], xi = xis[f], sg = sigmas[f], sl = slants[f];
  float c = cosf(th), s = sinf(th);
  float a0 = sl / sg, a1 = 1.f / sg;
  float gsum = 0.f, wr = 0.f, wi = 0.f;
  for (int p = threadIdx.x; p < NPIX; p += 256) {
    float gm = (float)((p >> 8) - 128);
    float gn = (float)((p & 255) - 128);
    float u = c * gm + s * gn;
    float vv = -s * gm + c * gn;
    float g = expf(-0.5f * (a0 * a0 * u * u + a1 * a1 * vv * vv));
    float sn, cn;
    sincosf(xi * u, &sn, &cn);
    gsum += g; wr += cn * g; wi += sn * g;
  }
  __shared__ float r0[256], r1[256], r2[256];
  int tid = threadIdx.x;
  r0[tid] = gsum; r1[tid] = wr; r2[tid] = wi;
  __syncthreads();
  for (int s2 = 128; s2 > 0; s2 >>= 1) {
    if (tid < s2) { r0[tid] += r0[tid + s2]; r1[tid] += r1[tid + s2]; r2[tid] += r2[tid + s2]; }
    __syncthreads();
  }
  if (tid == 0) { g_gs[f] = r0[0]; g_ws[f] = make_float2(r1[0], r2[0]); }
}

__global__ void k_filter_build(const float* theta, const float* xis,
                               const float* sigmas, const float* slants) {
  int gid = blockIdx.x * 256 + threadIdx.x;
  int f = gid >> 16;
  int p = gid & 65535;
  int i = p >> 8, jd = p & 255;
  float gm = (i < 128) ? (float)i : (float)(i - 256);
  float gn = (jd < 128) ? (float)jd : (float)(jd - 256);
  float2 val;
  if (f < 8) {
    float th = theta[f], xi = xis[f], sg = sigmas[f], sl = slants[f];
    float c = cosf(th), s = sinf(th);
    float u = c * gm + s * gn;
    float vv = -s * gm + c * gn;
    float a0 = sl / sg, a1 = 1.f / sg;
    float g = expf(-0.5f * (a0 * a0 * u * u + a1 * a1 * vv * vv));
    float sn, cn;
    sincosf(xi * u, &sn, &cn);
    float Kr = g_ws[f].x / g_gs[f];
    float Ki = g_ws[f].y / g_gs[f];
    float invn = sl / (TWO_PI * sg * sg);
    val = make_float2((cn - Kr) * g * invn, (sn - Ki) * g * invn);
  } else {
    const float sp = 3.2f;
    float g = expf(-0.5f * (gm * gm + gn * gn) / (sp * sp));
    val = make_float2(g / (TWO_PI * sp * sp), 0.f);
  }
  g_fA[gid] = val;
}

// ---------------- FFT passes ---------------------------------------------------
// Forward row pass: 16 rows/block, 16 threads/row (line = half warp -> syncwarp).
template <bool REAL_IN>
__global__ void __launch_bounds__(256, 4) k_frow(const void* in_, float2* out) {
  __shared__ float2 SM[16 * LSTRIDE];
  int t = threadIdx.x & 15, line = threadIdx.x >> 4;
  size_t base = ((size_t)blockIdx.x * 16 + line) << 8;
  float2 v[16];
  if (REAL_IN) {
    const float* in = (const float*)in_;
#pragma unroll
    for (int n1 = 0; n1 < 16; ++n1) v[n1] = make_float2(in[base + 16*n1 + t], 0.f);
  } else {
    const float2* in = (const float2*)in_;
#pragma unroll
    for (int n1 = 0; n1 < 16; ++n1) v[n1] = in[base + 16*n1 + t];
  }
  fft256_reg<-1, false>(v, SM + line * LSTRIDE, t);
#pragma unroll
  for (int k2 = 0; k2 < 16; ++k2)
    out[base + t + 16*k2] = v[PERM(k2)];
}

// Forward column pass: block covers 16 consecutive columns (c = tid&15 -> coalesced),
// 16 threads per column spanning warps -> block sync.
__global__ void __launch_bounds__(256, 4) k_fcol(const float2* in, float2* out) {
  __shared__ float2 SM[16 * LSTRIDE];
  int c = threadIdx.x & 15, t = threadIdx.x >> 4;
  int img = blockIdx.x >> 4;
  size_t base = ((size_t)img << 16) + ((blockIdx.x & 15) << 4) + c;
  float2 v[16];
#pragma unroll
  for (int n1 = 0; n1 < 16; ++n1)
    v[n1] = in[base + ((size_t)(16*n1 + t) << 8)];
  fft256_reg<-1, true>(v, SM + c * LSTRIDE, t);
#pragma unroll
  for (int k2 = 0; k2 < 16; ++k2)
    out[base + ((size_t)(t + 16*k2) << 8)] = v[PERM(k2)];
}

// Inverse column pass fused with pointwise filter multiply + 1/65536 scale.
template <int LOGNF>
__global__ void __launch_bounds__(256, 4) k_icolmul(const float2* in, const float2* filt,
                                                    float2* out, float scale) {
  __shared__ float2 SM[16 * LSTRIDE];
  int c = threadIdx.x & 15, t = threadIdx.x >> 4;
  int o = blockIdx.x >> 4;
  size_t cb = ((blockIdx.x & 15) << 4) + c;
  const float2* src = in + ((size_t)(o >> LOGNF) << 16);
  const float2* ff  = filt + ((size_t)(o & ((1 << LOGNF) - 1)) << 16);
  float2 v[16];
#pragma unroll
  for (int n1 = 0; n1 < 16; ++n1) {
    size_t a = cb + ((size_t)(16*n1 + t) << 8);
    float2 u = cmulf(src[a], ff[a]);
    v[n1] = make_float2(u.x * scale, u.y * scale);
  }
  fft256_reg<1, true>(v, SM + c * LSTRIDE, t);
  size_t ob = ((size_t)o << 16) + cb;
#pragma unroll
  for (int k2 = 0; k2 < 16; ++k2)
    out[ob + ((size_t)(t + 16*k2) << 8)] = v[PERM(k2)];
}

// Inverse row pass fused with real/abs + scatter to output channel layout.
// STAGE: 0 = S0 (real), 1 = U1 (abs, also write u1 buffer), 2 = U2 (abs).
template <int STAGE>
__global__ void __launch_bounds__(256, 4) k_irow_out(const float2* in, float* out, float* u1) {
  __shared__ float2 SM[16 * LSTRIDE];
  int t = threadIdx.x & 15, line = threadIdx.x >> 4;
  size_t gl = (size_t)blockIdx.x * 16 + line;
  int o = (int)(gl >> 8);
  int row = (int)(gl & 255);
  size_t base = gl << 8;
  float2 v[16];
#pragma unroll
  for (int n1 = 0; n1 < 16; ++n1) v[n1] = in[base + 16*n1 + t];
  fft256_reg<1, false>(v, SM + line * LSTRIDE, t);

  int b, ch;
  if (STAGE == 0) {
    b = o >> 1; ch = (o & 1) * 73;
  } else if (STAGE == 1) {
    int f = o & 7, bc = o >> 3;
    b = bc >> 1; ch = (bc & 1) * 73 + 1 + f;
  } else {
    int f2 = o & 7, tt = o >> 3;
    int f1 = tt & 7, bc = tt >> 3;
    b = bc >> 1; ch = (bc & 1) * 73 + 9 + f1 * 8 + f2;
  }
  size_t obase = (((size_t)(b * 146 + ch)) << 16) + ((size_t)row << 8);
#pragma unroll
  for (int k2 = 0; k2 < 16; ++k2) {
    float2 y = v[PERM(k2)];
    float val = (STAGE == 0) ? y.x : sqrtf(y.x * y.x + y.y * y.y);
    out[obase + t + 16*k2] = val;
    if (STAGE == 1) u1[base + t + 16*k2] = val;
  }
}

// ---------------- launch -------------------------------------------------------
extern "C" void kernel_launch(void* const* d_in, const int* in_sizes, int n_in,
                              void* d_out, int out_size) {
  (void)in_sizes; (void)n_in; (void)out_size;
  const float* x = (const float*)d_in[0];
  const float* theta = (const float*)d_in[1];
  const float* xis = (const float*)d_in[2];
  const float* sigmas = (const float*)d_in[3];
  const float* slants = (const float*)d_in[4];
  float* out = (float*)d_out;

  void* p;
  cudaGetSymbolAddress(&p, g_fA);  float2* fA = (float2*)p;
  cudaGetSymbolAddress(&p, g_fB);  float2* fB = (float2*)p;
  cudaGetSymbolAddress(&p, g_xT);  float2* xT = (float2*)p;
  cudaGetSymbolAddress(&p, g_Xh);  float2* Xh = (float2*)p;
  cudaGetSymbolAddress(&p, g_U1);  float* U1 = (float*)p;
  cudaGetSymbolAddress(&p, g_U1h); float2* U1h = (float2*)p;
  cudaGetSymbolAddress(&p, g_S);   float2* S = (float2*)p;

  const float inv = 1.f / 65536.f;

  // Filters: spatial build (+ifftshift) then fft2. psi_hat = fA[0..8), phi_hat = fA[8].
  k_filter_sums<<<8, 256>>>(theta, xis, sigmas, slants);
  k_filter_build<<<(9 * NPIX) / 256, 256>>>(theta, xis, sigmas, slants);
  k_frow<false><<<9 * 16, 256>>>(fA, fB);
  k_fcol<<<9 * 16, 256>>>(fB, fA);

  // Xh = fft2(x)
  k_frow<true><<<8 * 16, 256>>>(x, xT);
  k_fcol<<<8 * 16, 256>>>(xT, Xh);

  // S0 = ifft2(Xh * phi).real
  k_icolmul<0><<<8 * 16, 256>>>(Xh, fA + 8 * NPIX, S, inv);
  k_irow_out<0><<<8 * 16, 256>>>(S, out, nullptr);

  // U1 = |ifft2(Xh x psi)|  (64 images)
  k_icolmul<3><<<64 * 16, 256>>>(Xh, fA, S, inv);
  k_irow_out<1><<<64 * 16, 256>>>(S, out, U1);

  // U1h = fft2(U1)
  k_frow<true><<<64 * 16, 256>>>(U1, S);
  k_fcol<<<64 * 16, 256>>>(S, U1h);

  // U2 = |ifft2(U1h x psi)|  (512 images)
  k_icolmul<3><<<512 * 16, 256>>>(U1h, fA, S, inv);
  k_irow_out<2><<<512 * 16, 256>>>(S, out, nullptr);
}

// round 5
// speedup vs baseline: 3.0930x; 1.3790x over previous
#include <cuda_runtime.h>
#include <math.h>

#define NPIX 65536
#define TWO_PI 6.283185307179586f
#define LSTRIDE 273   // transpose smem stride (float2) per line
#define PSTRIDE 257   // private-stash smem stride (float2) per line

// ---------------- scratch (device globals) ------------------------------------
__device__ float2 g_fA[9 * NPIX];     // filter hats (psi 0..7, phi 8)
__device__ float2 g_fB[9 * NPIX];     // filter fft temp; later Sphi (8 img)
__device__ float2 g_xT[8 * NPIX];     // x row-FFT
__device__ float2 g_S2[64 * NPIX];    // U1 row-fwd-FFT
__device__ float2 g_S[512 * NPIX];    // [0..64): U1 mid (col-inv); later: U2 mid (512 img)
__device__ float  g_gs[8];
__device__ float2 g_ws[8];

__device__ __forceinline__ float2 cmulf(float2 a, float2 b) {
  return make_float2(a.x * b.x - a.y * b.y, a.x * b.y + a.y * b.x);
}
__device__ __forceinline__ float2 cadd(float2 a, float2 b){ return make_float2(a.x+b.x, a.y+b.y); }
__device__ __forceinline__ float2 csub(float2 a, float2 b){ return make_float2(a.x-b.x, a.y-b.y); }

template<int SGN>
__device__ __forceinline__ void dft4(float2& x0, float2& x1, float2& x2, float2& x3){
  float2 t0 = cadd(x0,x2), t1 = csub(x0,x2);
  float2 t2 = cadd(x1,x3), t3 = csub(x1,x3);
  float2 it3 = make_float2(-(float)SGN * t3.y, (float)SGN * t3.x);
  x0 = cadd(t0,t2);
  x1 = cadd(t1,it3);
  x2 = csub(t0,t2);
  x3 = csub(t1,it3);
}

// 16-pt DFT in registers. Input v[n] natural; output y[k0+4k1] at v[4k0+k1].
#define PERM(k) ((((k)&3)<<2)|((k)>>2))
template<int SGN>
__device__ __forceinline__ void fft16(float2 v[16]){
  const float C[10] = {1.f, 0.9238795325f, 0.7071067812f, 0.3826834324f, 0.f,
                       -0.3826834324f, -0.7071067812f, -0.9238795325f, -1.f, -0.9238795325f};
  const float S[10] = {0.f, 0.3826834324f, 0.7071067812f, 0.9238795325f, 1.f,
                       0.9238795325f, 0.7071067812f, 0.3826834324f, 0.f, -0.3826834324f};
#pragma unroll
  for (int n0 = 0; n0 < 4; ++n0)
    dft4<SGN>(v[n0], v[4+n0], v[8+n0], v[12+n0]);
#pragma unroll
  for (int n0 = 1; n0 < 4; ++n0)
#pragma unroll
    for (int k0 = 1; k0 < 4; ++k0) {
      int m = n0 * k0;
      float2 w = make_float2(C[m], (float)SGN * S[m]);
      v[n0 + 4*k0] = cmulf(v[n0 + 4*k0], w);
    }
#pragma unroll
  for (int k0 = 0; k0 < 4; ++k0)
    dft4<SGN>(v[4*k0+0], v[4*k0+1], v[4*k0+2], v[4*k0+3]);
}

// 256-pt FFT. Thread t (of 16 per line) holds x[16*n1+t] in v[n1].
// On exit: X[t+16*k2] is in v[PERM(k2)]. To chain along the same axis,
// copy v[PERM(k)] -> a[k]  (value at index 16k+t goes to input slot k).
template<int SGN, bool BSYNC>
__device__ __forceinline__ void fft256_reg(float2 v[16], float2* sm, int t){
  fft16<SGN>(v);
  if (BSYNC) __syncthreads(); else __syncwarp();   // guard smem reuse across calls
  float ang = (float)SGN * TWO_PI * (float)t * (1.f / 256.f);
  float sn, cs; __sincosf(ang, &sn, &cs);
  float2 w = make_float2(cs, sn);
  float2 tw = make_float2(1.f, 0.f);
#pragma unroll
  for (int k1 = 0; k1 < 16; ++k1) {
    sm[k1 * 17 + t] = cmulf(v[PERM(k1)], tw);
    tw = cmulf(tw, w);
  }
  if (BSYNC) __syncthreads(); else __syncwarp();
#pragma unroll
  for (int n2 = 0; n2 < 16; ++n2) v[n2] = sm[t * 17 + n2];
  fft16<SGN>(v);
}

// ---------------- filter construction -----------------------------------------
__global__ void k_filter_sums(const float* theta, const float* xis,
                              const float* sigmas, const float* slants) {
  int f = blockIdx.x;
  float th = theta[f], xi = xis[f], sg = sigmas[f], sl = slants[f];
  float c = cosf(th), s = sinf(th);
  float a0 = sl / sg, a1 = 1.f / sg;
  float gsum = 0.f, wr = 0.f, wi = 0.f;
  for (int p = threadIdx.x; p < NPIX; p += 256) {
    float gm = (float)((p >> 8) - 128);
    float gn = (float)((p & 255) - 128);
    float u = c * gm + s * gn;
    float vv = -s * gm + c * gn;
    float g = expf(-0.5f * (a0 * a0 * u * u + a1 * a1 * vv * vv));
    float sn, cn;
    sincosf(xi * u, &sn, &cn);
    gsum += g; wr += cn * g; wi += sn * g;
  }
  __shared__ float r0[256], r1[256], r2[256];
  int tid = threadIdx.x;
  r0[tid] = gsum; r1[tid] = wr; r2[tid] = wi;
  __syncthreads();
  for (int s2 = 128; s2 > 0; s2 >>= 1) {
    if (tid < s2) { r0[tid] += r0[tid + s2]; r1[tid] += r1[tid + s2]; r2[tid] += r2[tid + s2]; }
    __syncthreads();
  }
  if (tid == 0) { g_gs[f] = r0[0]; g_ws[f] = make_float2(r1[0], r2[0]); }
}

__global__ void k_filter_build(const float* theta, const float* xis,
                               const float* sigmas, const float* slants) {
  int gid = blockIdx.x * 256 + threadIdx.x;
  int f = gid >> 16;
  int p = gid & 65535;
  int i = p >> 8, jd = p & 255;
  float gm = (i < 128) ? (float)i : (float)(i - 256);
  float gn = (jd < 128) ? (float)jd : (float)(jd - 256);
  float2 val;
  if (f < 8) {
    float th = theta[f], xi = xis[f], sg = sigmas[f], sl = slants[f];
    float c = cosf(th), s = sinf(th);
    float u = c * gm + s * gn;
    float vv = -s * gm + c * gn;
    float a0 = sl / sg, a1 = 1.f / sg;
    float g = expf(-0.5f * (a0 * a0 * u * u + a1 * a1 * vv * vv));
    float sn, cn;
    sincosf(xi * u, &sn, &cn);
    float Kr = g_ws[f].x / g_gs[f];
    float Ki = g_ws[f].y / g_gs[f];
    float invn = sl / (TWO_PI * sg * sg);
    val = make_float2((cn - Kr) * g * invn, (sn - Ki) * g * invn);
  } else {
    const float sp = 3.2f;
    float g = expf(-0.5f * (gm * gm + gn * gn) / (sp * sp));
    val = make_float2(g / (TWO_PI * sp * sp), 0.f);
  }
  g_fA[gid] = val;
}

// ---------------- FFT passes ---------------------------------------------------
// Forward row pass: 16 rows/block, 16 threads/row.
template <bool REAL_IN>
__global__ void __launch_bounds__(256, 4) k_frow(const void* in_, float2* out) {
  __shared__ float2 SM[16 * LSTRIDE];
  int t = threadIdx.x & 15, line = threadIdx.x >> 4;
  size_t base = ((size_t)blockIdx.x * 16 + line) << 8;
  float2 v[16];
  if (REAL_IN) {
    const float* in = (const float*)in_;
#pragma unroll
    for (int n1 = 0; n1 < 16; ++n1) v[n1] = make_float2(in[base + 16*n1 + t], 0.f);
  } else {
    const float2* in = (const float2*)in_;
#pragma unroll
    for (int n1 = 0; n1 < 16; ++n1) v[n1] = in[base + 16*n1 + t];
  }
  fft256_reg<-1, false>(v, SM + line * LSTRIDE, t);
#pragma unroll
  for (int k2 = 0; k2 < 16; ++k2)
    out[base + t + 16*k2] = v[PERM(k2)];
}

// Forward column pass (used only for the 9 filters).
__global__ void __launch_bounds__(256, 4) k_fcol(const float2* in, float2* out) {
  __shared__ float2 SM[16 * LSTRIDE];
  int c = threadIdx.x & 15, t = threadIdx.x >> 4;
  int img = blockIdx.x >> 4;
  size_t base = ((size_t)img << 16) + ((blockIdx.x & 15) << 4) + c;
  float2 v[16];
#pragma unroll
  for (int n1 = 0; n1 < 16; ++n1)
    v[n1] = in[base + ((size_t)(16*n1 + t) << 8)];
  fft256_reg<-1, true>(v, SM + c * LSTRIDE, t);
#pragma unroll
  for (int k2 = 0; k2 < 16; ++k2)
    out[base + ((size_t)(t + 16*k2) << 8)] = v[PERM(k2)];
}

// Fused column kernel: fwd col FFT of source, then NF x (filter-mul + inv col FFT).
// Forward result stashed per-thread in SM2 (thread-private addresses, no sync).
// NF=9: x stage (psi 0..7 -> Spsi[img*8+f], phi -> Sphi[img]).
// NF=8: U2 stage (psi f2 -> Spsi[img*8+f2]).
template <int NF>
__global__ void __launch_bounds__(256, 3) k_fusedcol(const float2* in, const float2* filt,
                                                     float2* Spsi, float2* Sphi, float scale) {
  __shared__ float2 SM[16 * LSTRIDE];
  __shared__ float2 SM2[16 * PSTRIDE];
  int c = threadIdx.x & 15, t = threadIdx.x >> 4;
  int img = blockIdx.x >> 4;
  size_t cb = ((blockIdx.x & 15) << 4) + c;
  size_t base = ((size_t)img << 16) + cb;
  float2* priv = SM2 + c * PSTRIDE + t * 16;
  float2 v[16];
#pragma unroll
  for (int n1 = 0; n1 < 16; ++n1)
    v[n1] = in[base + ((size_t)(16*n1 + t) << 8)];
  fft256_reg<-1, true>(v, SM + c * LSTRIDE, t);
#pragma unroll
  for (int k = 0; k < 16; ++k) priv[k] = v[PERM(k)];   // priv[k] = Xhat[t+16k]

  for (int f = 0; f < NF; ++f) {
    const float2* ff = filt + ((size_t)f << 16);
#pragma unroll
    for (int n1 = 0; n1 < 16; ++n1) {
      float2 u = cmulf(priv[n1], ff[cb + ((size_t)(t + 16*n1) << 8)]);
      v[n1] = make_float2(u.x * scale, u.y * scale);
    }
    fft256_reg<1, true>(v, SM + c * LSTRIDE, t);
    float2* dst = (NF == 9 && f == 8) ? (Sphi + ((size_t)img << 16))
                                      : (Spsi + ((size_t)(img * 8 + f) << 16));
#pragma unroll
    for (int k2 = 0; k2 < 16; ++k2)
      dst[cb + ((size_t)(t + 16*k2) << 8)] = v[PERM(k2)];
  }
}

// U1 rows: inverse row FFT of mid, abs -> out channel, then fwd row FFT -> S2.
__global__ void __launch_bounds__(256, 4) k_U1rows(const float2* mid, float* out, float2* S2) {
  __shared__ float2 SM[16 * LSTRIDE];
  int t = threadIdx.x & 15, line = threadIdx.x >> 4;
  size_t gl = (size_t)blockIdx.x * 16 + line;
  int o = (int)(gl >> 8);
  int row = (int)(gl & 255);
  size_t base = gl << 8;
  float2 v[16];
#pragma unroll
  for (int n1 = 0; n1 < 16; ++n1) v[n1] = mid[base + 16*n1 + t];
  fft256_reg<1, false>(v, SM + line * LSTRIDE, t);

  int f = o & 7, bc = o >> 3;
  int b = bc >> 1, ch = (bc & 1) * 73 + 1 + f;
  size_t obase = (((size_t)(b * 146 + ch)) << 16) + ((size_t)row << 8);
  float2 a[16];
#pragma unroll
  for (int k = 0; k < 16; ++k) {
    float2 y = v[PERM(k)];
    float m = sqrtf(y.x * y.x + y.y * y.y);
    out[obase + t + 16*k] = m;
    a[k] = make_float2(m, 0.f);   // FIX: value at index 16k+t -> input slot k
  }
  fft256_reg<-1, false>(a, SM + line * LSTRIDE, t);
#pragma unroll
  for (int k2 = 0; k2 < 16; ++k2)
    S2[base + t + 16*k2] = a[PERM(k2)];
}

// Final inverse row pass: STAGE 0 = S0 (real), STAGE 2 = U2 (abs).
template <int STAGE>
__global__ void __launch_bounds__(256, 4) k_irow_out(const float2* in, float* out) {
  __shared__ float2 SM[16 * LSTRIDE];
  int t = threadIdx.x & 15, line = threadIdx.x >> 4;
  size_t gl = (size_t)blockIdx.x * 16 + line;
  int o = (int)(gl >> 8);
  int row = (int)(gl & 255);
  size_t base = gl << 8;
  float2 v[16];
#pragma unroll
  for (int n1 = 0; n1 < 16; ++n1) v[n1] = in[base + 16*n1 + t];
  fft256_reg<1, false>(v, SM + line * LSTRIDE, t);

  int b, ch;
  if (STAGE == 0) {
    b = o >> 1; ch = (o & 1) * 73;
  } else {
    int f2 = o & 7, tt = o >> 3;
    int f1 = tt & 7, bc = tt >> 3;
    b = bc >> 1; ch = (bc & 1) * 73 + 9 + f1 * 8 + f2;
  }
  size_t obase = (((size_t)(b * 146 + ch)) << 16) + ((size_t)row << 8);
#pragma unroll
  for (int k2 = 0; k2 < 16; ++k2) {
    float2 y = v[PERM(k2)];
    out[obase + t + 16*k2] = (STAGE == 0) ? y.x : sqrtf(y.x * y.x + y.y * y.y);
  }
}

// ---------------- launch -------------------------------------------------------
extern "C" void kernel_launch(void* const* d_in, const int* in_sizes, int n_in,
                              void* d_out, int out_size) {
  (void)in_sizes; (void)n_in; (void)out_size;
  const float* x = (const float*)d_in[0];
  const float* theta = (const float*)d_in[1];
  const float* xis = (const float*)d_in[2];
  const float* sigmas = (const float*)d_in[3];
  const float* slants = (const float*)d_in[4];
  float* out = (float*)d_out;

  void* p;
  cudaGetSymbolAddress(&p, g_fA); float2* fA = (float2*)p;
  cudaGetSymbolAddress(&p, g_fB); float2* fB = (float2*)p;
  cudaGetSymbolAddress(&p, g_xT); float2* xT = (float2*)p;
  cudaGetSymbolAddress(&p, g_S2); float2* S2 = (float2*)p;
  cudaGetSymbolAddress(&p, g_S);  float2* S  = (float2*)p;

  const float inv = 1.f / 65536.f;

  // Filters: spatial build (+ifftshift) then fft2 -> fA. (fB = temp)
  k_filter_sums<<<8, 256>>>(theta, xis, sigmas, slants);
  k_filter_build<<<(9 * NPIX) / 256, 256>>>(theta, xis, sigmas, slants);
  k_frow<false><<<9 * 16, 256>>>(fA, fB);
  k_fcol<<<9 * 16, 256>>>(fB, fA);

  // x row FFT
  k_frow<true><<<8 * 16, 256>>>(x, xT);

  // Fused: fwd col FFT of x + 9x (mul + inv col FFT).
  // psi mids -> S[0..64 img), phi mid -> fB (free now).
  k_fusedcol<9><<<8 * 16, 256>>>(xT, fA, S, fB, inv);

  // S0 rows: real -> out
  k_irow_out<0><<<8 * 16, 256>>>(fB, out);

  // U1 rows: abs -> out, fwd row FFT -> S2 (no U1 round trip)
  k_U1rows<<<64 * 16, 256>>>(S, out, S2);

  // Fused U2: fwd col FFT of S2 + 8x (mul + inv col FFT) -> S (512 img)
  k_fusedcol<8><<<64 * 16, 256>>>(S2, fA, S, nullptr, inv);

  // U2 rows: abs -> out
  k_irow_out<2><<<512 * 16, 256>>>(S, out);
}

// round 6
// speedup vs baseline: 3.5310x; 1.1416x over previous
#include <cuda_runtime.h>
#include <cuda_fp16.h>
#include <math.h>

#define NPIX 65536
#define TWO_PI 6.283185307179586f
#define LSTRIDE 273   // transpose smem stride (float2) per line
#define PSTRIDE 257   // private-stash smem stride (float2) per line

// ---------------- scratch (device globals) ------------------------------------
__device__ float2  g_fA[9 * NPIX];    // filter hats (psi 0..7, phi 8)
__device__ float2  g_fB[9 * NPIX];    // filter fft temp; later Sphi (8 img)
__device__ float2  g_xT[8 * NPIX];    // x row-FFT
__device__ float2  g_S2[64 * NPIX];   // U1 row-fwd-FFT (U1h)
__device__ float2  g_S[64 * NPIX];    // U1 mid (col-inv), float2
__device__ __half2 g_Sh[512 * NPIX];  // U2 mid (col-inv), half2  (128 MB)
__device__ float   g_gs[8];
__device__ float2  g_ws[8];

__device__ __forceinline__ float2 cmulf(float2 a, float2 b) {
  return make_float2(a.x * b.x - a.y * b.y, a.x * b.y + a.y * b.x);
}
__device__ __forceinline__ float2 cadd(float2 a, float2 b){ return make_float2(a.x+b.x, a.y+b.y); }
__device__ __forceinline__ float2 csub(float2 a, float2 b){ return make_float2(a.x-b.x, a.y-b.y); }

template<int SGN>
__device__ __forceinline__ void dft4(float2& x0, float2& x1, float2& x2, float2& x3){
  float2 t0 = cadd(x0,x2), t1 = csub(x0,x2);
  float2 t2 = cadd(x1,x3), t3 = csub(x1,x3);
  float2 it3 = make_float2(-(float)SGN * t3.y, (float)SGN * t3.x);
  x0 = cadd(t0,t2);
  x1 = cadd(t1,it3);
  x2 = csub(t0,t2);
  x3 = csub(t1,it3);
}

// 16-pt DFT in registers. Input v[n] natural; output y[k0+4k1] at v[4k0+k1].
#define PERM(k) ((((k)&3)<<2)|((k)>>2))
template<int SGN>
__device__ __forceinline__ void fft16(float2 v[16]){
  const float C[10] = {1.f, 0.9238795325f, 0.7071067812f, 0.3826834324f, 0.f,
                       -0.3826834324f, -0.7071067812f, -0.9238795325f, -1.f, -0.9238795325f};
  const float S[10] = {0.f, 0.3826834324f, 0.7071067812f, 0.9238795325f, 1.f,
                       0.9238795325f, 0.7071067812f, 0.3826834324f, 0.f, -0.3826834324f};
#pragma unroll
  for (int n0 = 0; n0 < 4; ++n0)
    dft4<SGN>(v[n0], v[4+n0], v[8+n0], v[12+n0]);
#pragma unroll
  for (int n0 = 1; n0 < 4; ++n0)
#pragma unroll
    for (int k0 = 1; k0 < 4; ++k0) {
      int m = n0 * k0;
      float2 w = make_float2(C[m], (float)SGN * S[m]);
      v[n0 + 4*k0] = cmulf(v[n0 + 4*k0], w);
    }
#pragma unroll
  for (int k0 = 0; k0 < 4; ++k0)
    dft4<SGN>(v[4*k0+0], v[4*k0+1], v[4*k0+2], v[4*k0+3]);
}

// 256-pt FFT. Thread t (of 16 per line) holds x[16*n1+t] in v[n1].
// On exit: X[t+16*k2] is in v[PERM(k2)]. To chain along the same axis,
// copy v[PERM(k)] -> a[k]  (value at index 16k+t goes to input slot k).
template<int SGN, bool BSYNC>
__device__ __forceinline__ void fft256_reg(float2 v[16], float2* sm, int t){
  fft16<SGN>(v);
  if (BSYNC) __syncthreads(); else __syncwarp();   // guard smem reuse across calls
  float ang = (float)SGN * TWO_PI * (float)t * (1.f / 256.f);
  float sn, cs; __sincosf(ang, &sn, &cs);
  float2 w = make_float2(cs, sn);
  float2 tw = make_float2(1.f, 0.f);
#pragma unroll
  for (int k1 = 0; k1 < 16; ++k1) {
    sm[k1 * 17 + t] = cmulf(v[PERM(k1)], tw);
    tw = cmulf(tw, w);
  }
  if (BSYNC) __syncthreads(); else __syncwarp();
#pragma unroll
  for (int n2 = 0; n2 < 16; ++n2) v[n2] = sm[t * 17 + n2];
  fft16<SGN>(v);
}

// ---------------- filter construction -----------------------------------------
__global__ void k_filter_sums(const float* theta, const float* xis,
                              const float* sigmas, const float* slants) {
  int f = blockIdx.x;
  float th = theta[f], xi = xis[f], sg = sigmas[f], sl = slants[f];
  float c = cosf(th), s = sinf(th);
  float a0 = sl / sg, a1 = 1.f / sg;
  float gsum = 0.f, wr = 0.f, wi = 0.f;
  for (int p = threadIdx.x; p < NPIX; p += 256) {
    float gm = (float)((p >> 8) - 128);
    float gn = (float)((p & 255) - 128);
    float u = c * gm + s * gn;
    float vv = -s * gm + c * gn;
    float g = expf(-0.5f * (a0 * a0 * u * u + a1 * a1 * vv * vv));
    float sn, cn;
    sincosf(xi * u, &sn, &cn);
    gsum += g; wr += cn * g; wi += sn * g;
  }
  __shared__ float r0[256], r1[256], r2[256];
  int tid = threadIdx.x;
  r0[tid] = gsum; r1[tid] = wr; r2[tid] = wi;
  __syncthreads();
  for (int s2 = 128; s2 > 0; s2 >>= 1) {
    if (tid < s2) { r0[tid] += r0[tid + s2]; r1[tid] += r1[tid + s2]; r2[tid] += r2[tid + s2]; }
    __syncthreads();
  }
  if (tid == 0) { g_gs[f] = r0[0]; g_ws[f] = make_float2(r1[0], r2[0]); }
}

__global__ void k_filter_build(const float* theta, const float* xis,
                               const float* sigmas, const float* slants) {
  int gid = blockIdx.x * 256 + threadIdx.x;
  int f = gid >> 16;
  int p = gid & 65535;
  int i = p >> 8, jd = p & 255;
  float gm = (i < 128) ? (float)i : (float)(i - 256);
  float gn = (jd < 128) ? (float)jd : (float)(jd - 256);
  float2 val;
  if (f < 8) {
    float th = theta[f], xi = xis[f], sg = sigmas[f], sl = slants[f];
    float c = cosf(th), s = sinf(th);
    float u = c * gm + s * gn;
    float vv = -s * gm + c * gn;
    float a0 = sl / sg, a1 = 1.f / sg;
    float g = expf(-0.5f * (a0 * a0 * u * u + a1 * a1 * vv * vv));
    float sn, cn;
    sincosf(xi * u, &sn, &cn);
    float Kr = g_ws[f].x / g_gs[f];
    float Ki = g_ws[f].y / g_gs[f];
    float invn = sl / (TWO_PI * sg * sg);
    val = make_float2((cn - Kr) * g * invn, (sn - Ki) * g * invn);
  } else {
    const float sp = 3.2f;
    float g = expf(-0.5f * (gm * gm + gn * gn) / (sp * sp));
    val = make_float2(g / (TWO_PI * sp * sp), 0.f);
  }
  g_fA[gid] = val;
}

// ---------------- FFT passes ---------------------------------------------------
// Forward row pass: 16 rows/block, 16 threads/row.
template <bool REAL_IN>
__global__ void __launch_bounds__(256, 4) k_frow(const void* in_, float2* out) {
  __shared__ float2 SM[16 * LSTRIDE];
  int t = threadIdx.x & 15, line = threadIdx.x >> 4;
  size_t base = ((size_t)blockIdx.x * 16 + line) << 8;
  float2 v[16];
  if (REAL_IN) {
    const float* in = (const float*)in_;
#pragma unroll
    for (int n1 = 0; n1 < 16; ++n1) v[n1] = make_float2(in[base + 16*n1 + t], 0.f);
  } else {
    const float2* in = (const float2*)in_;
#pragma unroll
    for (int n1 = 0; n1 < 16; ++n1) v[n1] = in[base + 16*n1 + t];
  }
  fft256_reg<-1, false>(v, SM + line * LSTRIDE, t);
#pragma unroll
  for (int k2 = 0; k2 < 16; ++k2)
    out[base + t + 16*k2] = v[PERM(k2)];
}

// Forward column pass (used only for the 9 filters).
__global__ void __launch_bounds__(256, 4) k_fcol(const float2* in, float2* out) {
  __shared__ float2 SM[16 * LSTRIDE];
  int c = threadIdx.x & 15, t = threadIdx.x >> 4;
  int img = blockIdx.x >> 4;
  size_t base = ((size_t)img << 16) + ((blockIdx.x & 15) << 4) + c;
  float2 v[16];
#pragma unroll
  for (int n1 = 0; n1 < 16; ++n1)
    v[n1] = in[base + ((size_t)(16*n1 + t) << 8)];
  fft256_reg<-1, true>(v, SM + c * LSTRIDE, t);
#pragma unroll
  for (int k2 = 0; k2 < 16; ++k2)
    out[base + ((size_t)(t + 16*k2) << 8)] = v[PERM(k2)];
}

// Fused column kernel: fwd col FFT of source, then NF x (filter-mul + inv col FFT).
// Forward result stashed per-thread in SM2 (thread-private addresses, no sync).
// NF=9 (float2 out): x stage (psi 0..7 -> Spsi[img*8+f], phi -> Sphi[img]).
// NF=8 (half2 out):  U2 stage (psi f2 -> Spsi[img*8+f2]).
template <int NF, bool HALF_OUT>
__global__ void __launch_bounds__(256, 3) k_fusedcol(const float2* in, const float2* filt,
                                                     void* Spsi_, float2* Sphi, float scale) {
  __shared__ float2 SM[16 * LSTRIDE];
  __shared__ float2 SM2[16 * PSTRIDE];
  int c = threadIdx.x & 15, t = threadIdx.x >> 4;
  int img = blockIdx.x >> 4;
  size_t cb = ((blockIdx.x & 15) << 4) + c;
  size_t base = ((size_t)img << 16) + cb;
  float2* priv = SM2 + c * PSTRIDE + t * 16;
  float2 v[16];
#pragma unroll
  for (int n1 = 0; n1 < 16; ++n1)
    v[n1] = in[base + ((size_t)(16*n1 + t) << 8)];
  fft256_reg<-1, true>(v, SM + c * LSTRIDE, t);
#pragma unroll
  for (int k = 0; k < 16; ++k) priv[k] = v[PERM(k)];   // priv[k] = Xhat[t+16k]

  for (int f = 0; f < NF; ++f) {
    const float2* ff = filt + ((size_t)f << 16);
#pragma unroll
    for (int n1 = 0; n1 < 16; ++n1) {
      float2 u = cmulf(priv[n1], ff[cb + ((size_t)(t + 16*n1) << 8)]);
      v[n1] = make_float2(u.x * scale, u.y * scale);
    }
    fft256_reg<1, true>(v, SM + c * LSTRIDE, t);
    if (NF == 9 && f == 8) {
      float2* dst = Sphi + ((size_t)img << 16);
#pragma unroll
      for (int k2 = 0; k2 < 16; ++k2)
        dst[cb + ((size_t)(t + 16*k2) << 8)] = v[PERM(k2)];
    } else if (HALF_OUT) {
      __half2* dst = (__half2*)Spsi_ + ((size_t)(img * 8 + f) << 16);
#pragma unroll
      for (int k2 = 0; k2 < 16; ++k2) {
        float2 y = v[PERM(k2)];
        dst[cb + ((size_t)(t + 16*k2) << 8)] = __floats2half2_rn(y.x, y.y);
      }
    } else {
      float2* dst = (float2*)Spsi_ + ((size_t)(img * 8 + f) << 16);
#pragma unroll
      for (int k2 = 0; k2 < 16; ++k2)
        dst[cb + ((size_t)(t + 16*k2) << 8)] = v[PERM(k2)];
    }
  }
}

// U1 rows: inverse row FFT of mid, abs -> out channel, then fwd row FFT -> S2.
__global__ void __launch_bounds__(256, 4) k_U1rows(const float2* mid, float* out, float2* S2) {
  __shared__ float2 SM[16 * LSTRIDE];
  int t = threadIdx.x & 15, line = threadIdx.x >> 4;
  size_t gl = (size_t)blockIdx.x * 16 + line;
  int o = (int)(gl >> 8);
  int row = (int)(gl & 255);
  size_t base = gl << 8;
  float2 v[16];
#pragma unroll
  for (int n1 = 0; n1 < 16; ++n1) v[n1] = mid[base + 16*n1 + t];
  fft256_reg<1, false>(v, SM + line * LSTRIDE, t);

  int f = o & 7, bc = o >> 3;
  int b = bc >> 1, ch = (bc & 1) * 73 + 1 + f;
  size_t obase = (((size_t)(b * 146 + ch)) << 16) + ((size_t)row << 8);
  float2 a[16];
#pragma unroll
  for (int k = 0; k < 16; ++k) {
    float2 y = v[PERM(k)];
    float m = sqrtf(y.x * y.x + y.y * y.y);
    out[obase + t + 16*k] = m;
    a[k] = make_float2(m, 0.f);   // value at index 16k+t -> input slot k
  }
  fft256_reg<-1, false>(a, SM + line * LSTRIDE, t);
#pragma unroll
  for (int k2 = 0; k2 < 16; ++k2)
    S2[base + t + 16*k2] = a[PERM(k2)];
}

// Final inverse row pass: STAGE 0 = S0 (real, float2 in), STAGE 2 = U2 (abs, half2 in).
template <int STAGE>
__global__ void __launch_bounds__(256, 4) k_irow_out(const void* in_, float* out) {
  __shared__ float2 SM[16 * LSTRIDE];
  int t = threadIdx.x & 15, line = threadIdx.x >> 4;
  size_t gl = (size_t)blockIdx.x * 16 + line;
  int o = (int)(gl >> 8);
  int row = (int)(gl & 255);
  size_t base = gl << 8;
  float2 v[16];
  if (STAGE == 2) {
    const __half2* in = (const __half2*)in_;
#pragma unroll
    for (int n1 = 0; n1 < 16; ++n1) v[n1] = __half22float2(in[base + 16*n1 + t]);
  } else {
    const float2* in = (const float2*)in_;
#pragma unroll
    for (int n1 = 0; n1 < 16; ++n1) v[n1] = in[base + 16*n1 + t];
  }
  fft256_reg<1, false>(v, SM + line * LSTRIDE, t);

  int b, ch;
  if (STAGE == 0) {
    b = o >> 1; ch = (o & 1) * 73;
  } else {
    int f2 = o & 7, tt = o >> 3;
    int f1 = tt & 7, bc = tt >> 3;
    b = bc >> 1; ch = (bc & 1) * 73 + 9 + f1 * 8 + f2;
  }
  size_t obase = (((size_t)(b * 146 + ch)) << 16) + ((size_t)row << 8);
#pragma unroll
  for (int k2 = 0; k2 < 16; ++k2) {
    float2 y = v[PERM(k2)];
    out[obase + t + 16*k2] = (STAGE == 0) ? y.x : sqrtf(y.x * y.x + y.y * y.y);
  }
}

// ---------------- launch -------------------------------------------------------
extern "C" void kernel_launch(void* const* d_in, const int* in_sizes, int n_in,
                              void* d_out, int out_size) {
  (void)in_sizes; (void)n_in; (void)out_size;
  const float* x = (const float*)d_in[0];
  const float* theta = (const float*)d_in[1];
  const float* xis = (const float*)d_in[2];
  const float* sigmas = (const float*)d_in[3];
  const float* slants = (const float*)d_in[4];
  float* out = (float*)d_out;

  void* p;
  cudaGetSymbolAddress(&p, g_fA); float2* fA = (float2*)p;
  cudaGetSymbolAddress(&p, g_fB); float2* fB = (float2*)p;
  cudaGetSymbolAddress(&p, g_xT); float2* xT = (float2*)p;
  cudaGetSymbolAddress(&p, g_S2); float2* S2 = (float2*)p;
  cudaGetSymbolAddress(&p, g_S);  float2* S  = (float2*)p;
  cudaGetSymbolAddress(&p, g_Sh); __half2* Sh = (__half2*)p;

  const float inv = 1.f / 65536.f;

  // Filters: spatial build (+ifftshift) then fft2 -> fA. (fB = temp)
  k_filter_sums<<<8, 256>>>(theta, xis, sigmas, slants);
  k_filter_build<<<(9 * NPIX) / 256, 256>>>(theta, xis, sigmas, slants);
  k_frow<false><<<9 * 16, 256>>>(fA, fB);
  k_fcol<<<9 * 16, 256>>>(fB, fA);

  // x row FFT
  k_frow<true><<<8 * 16, 256>>>(x, xT);

  // Fused: fwd col FFT of x + 9x (mul + inv col FFT).
  // psi mids (float2) -> S, phi mid -> fB (free now).
  k_fusedcol<9, false><<<8 * 16, 256>>>(xT, fA, S, fB, inv);

  // S0 rows: real -> out
  k_irow_out<0><<<8 * 16, 256>>>(fB, out);

  // U1 rows: abs -> out, fwd row FFT -> S2 (no U1 round trip)
  k_U1rows<<<64 * 16, 256>>>(S, out, S2);

  // Fused U2: fwd col FFT of S2 + 8x (mul + inv col FFT) -> Sh (half2, 512 img)
  k_fusedcol<8, true><<<64 * 16, 256>>>(S2, fA, Sh, nullptr, inv);

  // U2 rows: abs -> out
  k_irow_out<2><<<512 * 16, 256>>>(Sh, out);
}